// round 6
// baseline (speedup 1.0000x reference)
#include <cuda_runtime.h>

// RelationCrossing: feats (R=8, N, K=8, d=64) fp32, rel_attn (8, 64) fp32.
// scores[r,n,k] = leaky_relu(dot(feats[r,n,k,:], rel_attn[k,:]), 0.2)
// attn = softmax over r; out[n,k,:] = sum_r attn[r,n,k] * feats[r,n,k,:]
//
// R1 register-resident float4 scheme + PERSISTENT GRID + SOFTWARE PIPELINE:
// each thread grid-strides over tiles; the NEXT tile's 8 LDG.128 are issued
// before the CURRENT tile's shuffle/softmax/FMA tail, so every warp keeps
// 8 loads continuously in flight instead of going load-silent for ~250 cyc
// per tile. 912 CTAs (persistent) removes ~780 wave transitions.
// feats read once (1.638 GB), out written once (0.205 GB) — traffic floor.

#define R 8
#define NEG_SLOPE 0.2f

__global__ __launch_bounds__(128, 6) void relation_crossing_kernel(
    const float4* __restrict__ feats,   // R * N * 128 float4s
    const float4* __restrict__ rel,     // 128 float4s (8 heads * 16 quarters)
    float4* __restrict__ out,           // N * 128 float4s
    int total4,                         // N * 128
    long long rel_stride4)              // N * 128 (float4 stride between relations)
{
    const int stride = gridDim.x * blockDim.x;
    int idx = blockIdx.x * blockDim.x + threadIdx.x;
    if (idx >= total4) return;

    // Prologue: load tile 0.
    float4 f[R];
#pragma unroll
    for (int r = 0; r < R; r++)
        f[r] = feats[(long long)r * rel_stride4 + idx];

    while (true) {
        int next = idx + stride;                 // block-uniform condition
        bool has_next = next < total4;

        // Prefetch next tile FIRST — in flight during this tile's tail.
        float4 g[R];
        if (has_next) {
#pragma unroll
            for (int r = 0; r < R; r++)
                g[r] = feats[(long long)r * rel_stride4 + next];
        }

        // idx = n*128 + k*16 + q; rel index = k*16+q (L1-resident, 2 KB).
        float4 ra = __ldg(&rel[idx & 127]);

        float s[R];
#pragma unroll
        for (int r = 0; r < R; r++)
            s[r] = f[r].x * ra.x + f[r].y * ra.y + f[r].z * ra.z + f[r].w * ra.w;

        // 16-lane butterfly reduce (warp-aligned head groups).
#pragma unroll
        for (int off = 8; off >= 1; off >>= 1) {
#pragma unroll
            for (int r = 0; r < R; r++)
                s[r] += __shfl_xor_sync(0xffffffffu, s[r], off);
        }

        // leaky_relu + softmax over relations.
        float m = -3.4e38f;
#pragma unroll
        for (int r = 0; r < R; r++) {
            s[r] = (s[r] > 0.0f) ? s[r] : NEG_SLOPE * s[r];
            m = fmaxf(m, s[r]);
        }
        float sum = 0.0f;
#pragma unroll
        for (int r = 0; r < R; r++) {
            s[r] = __expf(s[r] - m);
            sum += s[r];
        }
        float inv = __frcp_rn(sum);

        float4 o = make_float4(0.f, 0.f, 0.f, 0.f);
#pragma unroll
        for (int r = 0; r < R; r++) {
            float w = s[r] * inv;
            o.x = fmaf(w, f[r].x, o.x);
            o.y = fmaf(w, f[r].y, o.y);
            o.z = fmaf(w, f[r].z, o.z);
            o.w = fmaf(w, f[r].w, o.w);
        }
        out[idx] = o;

        if (!has_next) break;
#pragma unroll
        for (int r = 0; r < R; r++) f[r] = g[r];
        idx = next;
    }
}

extern "C" void kernel_launch(void* const* d_in, const int* in_sizes, int n_in,
                              void* d_out, int out_size)
{
    const float4* feats = (const float4*)d_in[0];  // (8, N, 512) fp32
    const float4* rel   = (const float4*)d_in[1];  // (8, 64) fp32
    float4* out = (float4*)d_out;                  // (N, 512) fp32

    long long elems_per_rel = (long long)in_sizes[0] / R;   // N*512 floats
    int total4 = (int)(elems_per_rel / 4);                  // N*128 float4
    long long rel_stride4 = total4;

    // Persistent grid: 6 CTAs/SM x 152 SMs = 912 CTAs of 128 threads.
    int threads = 128;
    int blocks = 912;
    int max_blocks = (total4 + threads - 1) / threads;
    if (blocks > max_blocks) blocks = max_blocks;
    relation_crossing_kernel<<<blocks, threads>>>(feats, rel, out, total4, rel_stride4);
}

// round 7
// speedup vs baseline: 1.2329x; 1.2329x over previous
#include <cuda_runtime.h>

// RelationCrossing: feats (R=8, N, K=8, d=64) fp32, rel_attn (8, 64) fp32.
// scores[r,n,k] = leaky_relu(dot(feats[r,n,k,:], rel_attn[k,:]), 0.2)
// attn = softmax over r; out[n,k,:] = sum_r attn[r,n,k] * feats[r,n,k,:]
//
// TWO-PASS / REGISTER-LIGHT variant of the R1 scheme:
//   Pass 1 loads each of the 8 relation float4s, folds it into the dot
//   partial immediately, and DISCARDS it — no f[8] array (32 regs) lives
//   across the shuffle/softmax tail. Pass 2 re-loads the same 8 float4s for
//   the weighted sum; reuse distance is a few hundred cycles vs ~20K-cycle
//   L2 residency at this stream rate, so pass 2 hits L2 (234-262 cyc), not
//   DRAM. Registers drop ~54 -> ~40 => 6 CTAs/SM = 48 warps (1.5x R1), and
//   each warp now has two load phases per tile -> continuous DRAM demand.
// DRAM traffic unchanged: feats 1.638 GB once, out 0.205 GB once.

#define R 8
#define NEG_SLOPE 0.2f

__global__ __launch_bounds__(256, 6) void relation_crossing_kernel(
    const float4* __restrict__ feats,   // R * N * 128 float4s
    const float4* __restrict__ rel,     // 128 float4s (8 heads * 16 quarters)
    float4* __restrict__ out,           // N * 128 float4s
    int total4,                         // N * 128
    long long rel_stride4)              // N * 128 (float4 stride between relations)
{
    int idx = blockIdx.x * blockDim.x + threadIdx.x;
    if (idx >= total4) return;

    // idx = n*128 + k*16 + q  (k = head, q = d-quarter). rel index = k*16+q.
    float4 ra = __ldg(&rel[idx & 127]);

    const float4* p = feats + idx;

    // Pass 1: dot partials; values consumed immediately, not kept.
    float s[R];
#pragma unroll
    for (int r = 0; r < R; r++) {
        float4 f = p[(long long)r * rel_stride4];
        s[r] = f.x * ra.x + f.y * ra.y + f.z * ra.z + f.w * ra.w;
    }

    // 16-lane butterfly reduce (head groups are warp-aligned).
#pragma unroll
    for (int off = 8; off >= 1; off >>= 1) {
#pragma unroll
        for (int r = 0; r < R; r++)
            s[r] += __shfl_xor_sync(0xffffffffu, s[r], off);
    }

    // leaky_relu + softmax over relations (identical across the group).
    float m = -3.4e38f;
#pragma unroll
    for (int r = 0; r < R; r++) {
        s[r] = (s[r] > 0.0f) ? s[r] : NEG_SLOPE * s[r];
        m = fmaxf(m, s[r]);
    }
    float sum = 0.0f;
#pragma unroll
    for (int r = 0; r < R; r++) {
        s[r] = __expf(s[r] - m);
        sum += s[r];
    }
    float inv = __frcp_rn(sum);

    // Pass 2: re-load (L2 hits) and accumulate the weighted sum.
    float4 o = make_float4(0.f, 0.f, 0.f, 0.f);
#pragma unroll
    for (int r = 0; r < R; r++) {
        float4 f = p[(long long)r * rel_stride4];
        float w = s[r] * inv;
        o.x = fmaf(w, f.x, o.x);
        o.y = fmaf(w, f.y, o.y);
        o.z = fmaf(w, f.z, o.z);
        o.w = fmaf(w, f.w, o.w);
    }
    __stcs(&out[idx], o);
}

extern "C" void kernel_launch(void* const* d_in, const int* in_sizes, int n_in,
                              void* d_out, int out_size)
{
    const float4* feats = (const float4*)d_in[0];  // (8, N, 512) fp32
    const float4* rel   = (const float4*)d_in[1];  // (8, 64) fp32
    float4* out = (float4*)d_out;                  // (N, 512) fp32

    long long elems_per_rel = (long long)in_sizes[0] / R;   // N*512 floats
    int total4 = (int)(elems_per_rel / 4);                  // N*128 float4
    long long rel_stride4 = total4;

    int threads = 256;
    int blocks = (total4 + threads - 1) / threads;
    relation_crossing_kernel<<<blocks, threads>>>(feats, rel, out, total4, rel_stride4);
}

// round 8
// speedup vs baseline: 1.2696x; 1.0298x over previous
#include <cuda_runtime.h>

// RelationCrossing: feats (R=8, N, K=8, d=64) fp32, rel_attn (8, 64) fp32.
// scores[r,n,k] = leaky_relu(dot(feats[r,n,k,:], rel_attn[k,:]), 0.2)
// attn = softmax over r; out[n,k,:] = sum_r attn[r,n,k] * feats[r,n,k,:]
//
// R1 register-resident float4 scheme (best: 254.4us, DRAM 91.8%), unchanged
// dataflow, with ONE delta: __launch_bounds__(256, 5) caps the ptxas register
// budget at 48 (vs 54), lifting residency from 4 to 5 CTAs/SM (40 warps).
// The squeeze should come from address-math rematerialization, not spills —
// no extra instructions on the per-tile critical path.
// feats read once (1.638 GB), out written once (0.205 GB) — traffic floor.

#define R 8
#define NEG_SLOPE 0.2f

__global__ __launch_bounds__(256, 5) void relation_crossing_kernel(
    const float4* __restrict__ feats,   // R * N * 128 float4s
    const float4* __restrict__ rel,     // 128 float4s (8 heads * 16 quarters)
    float4* __restrict__ out,           // N * 128 float4s
    int total4,                         // N * 128
    long long rel_stride4)              // N * 128 (float4 stride between relations)
{
    int idx = blockIdx.x * blockDim.x + threadIdx.x;
    if (idx >= total4) return;

    // idx = n*128 + k*16 + q  (k = head, q = d-quarter). rel index = k*16+q.
    float4 ra = __ldg(&rel[idx & 127]);

    // Front-batched loads: 8 independent LDG.128, scoreboard-interleaved.
    float4 f[R];
    float s[R];
#pragma unroll
    for (int r = 0; r < R; r++) {
        f[r] = feats[(long long)r * rel_stride4 + idx];
        s[r] = f[r].x * ra.x + f[r].y * ra.y + f[r].z * ra.z + f[r].w * ra.w;
    }

    // Reduce dot products across the 16-thread group covering this head.
    // Groups of 16 are warp-aligned; 4 butterfly levels, 8 independent values
    // per level so the serial chain is 4 SHFL latencies.
#pragma unroll
    for (int off = 8; off >= 1; off >>= 1) {
#pragma unroll
        for (int r = 0; r < R; r++)
            s[r] += __shfl_xor_sync(0xffffffffu, s[r], off);
    }

    // leaky_relu + softmax over relations (identical across the 16-lane group).
    float m = -3.4e38f;
#pragma unroll
    for (int r = 0; r < R; r++) {
        s[r] = (s[r] > 0.0f) ? s[r] : NEG_SLOPE * s[r];
        m = fmaxf(m, s[r]);
    }
    float sum = 0.0f;
#pragma unroll
    for (int r = 0; r < R; r++) {
        s[r] = __expf(s[r] - m);
        sum += s[r];
    }
    float inv = __frcp_rn(sum);

    float4 o = make_float4(0.f, 0.f, 0.f, 0.f);
#pragma unroll
    for (int r = 0; r < R; r++) {
        float w = s[r] * inv;
        o.x = fmaf(w, f[r].x, o.x);
        o.y = fmaf(w, f[r].y, o.y);
        o.z = fmaf(w, f[r].z, o.z);
        o.w = fmaf(w, f[r].w, o.w);
    }
    out[idx] = o;
}

extern "C" void kernel_launch(void* const* d_in, const int* in_sizes, int n_in,
                              void* d_out, int out_size)
{
    const float4* feats = (const float4*)d_in[0];  // (8, N, 512) fp32
    const float4* rel   = (const float4*)d_in[1];  // (8, 64) fp32
    float4* out = (float4*)d_out;                  // (N, 512) fp32

    long long elems_per_rel = (long long)in_sizes[0] / R;   // N*512 floats
    int total4 = (int)(elems_per_rel / 4);                  // N*128 float4
    long long rel_stride4 = total4;

    int threads = 256;
    int blocks = (total4 + threads - 1) / threads;
    relation_crossing_kernel<<<blocks, threads>>>(feats, rel, out, total4, rel_stride4);
}